// round 15
// baseline (speedup 1.0000x reference)
#include <cuda_runtime.h>
#include <cuda_fp16.h>
#include <cstdint>
#include <cstddef>

// ---------------------------------------------------------------------------
// MultiHeadAttention: y = proj( causal_attention( x @ W_attn + b_attn ) )
// B=8, T=1024, C=768, H=12, hd=64
// HMMA fp16; precision placement (calibrated ~6e-4):
//   - x hi/lo into Q columns; Q hi/lo into S=QK^T.
//   - K/V, P, y, W: single fp16.
// v8: QKV GEMM uses 128x256 CTA tiles (fewer smem fills + barriers per MMA);
//     attention exp via raw ex2.approx with folded log2e scale.
// ---------------------------------------------------------------------------

#define B_  8
#define T_  1024
#define C_  768
#define H_  12
#define HD_ 64
#define M_ROWS (B_ * T_)          // 8192
#define QKV_N  (3 * C_)           // 2304
#define K_     C_                 // 768

// ---------------- device scratch (no allocation allowed) -------------------
__device__ __half g_qh[B_ * H_ * T_ * HD_], g_ql[B_ * H_ * T_ * HD_];
__device__ __half g_kh[B_ * H_ * T_ * HD_];
__device__ __half g_vh[B_ * H_ * T_ * HD_];

__device__ __half g_xh[M_ROWS * K_], g_xl[M_ROWS * K_];
__device__ __half g_yh[M_ROWS * K_];                      // attn out (single fp16)
__device__ __half g_wah[QKV_N * K_];                      // W_attn^T [N,K]
__device__ __half g_wph[C_ * K_];                         // W_proj^T [N,K]

// ---------------- small PTX helpers (sm_80-level only) ---------------------
__device__ __forceinline__ uint32_t smem_to_u32(const void* p) {
    uint32_t a;
    asm("{ .reg .u64 t; cvta.to.shared.u64 t, %1; cvt.u32.u64 %0, t; }"
        : "=r"(a) : "l"(p));
    return a;
}
__device__ __forceinline__ void ldm_x4(uint32_t* r, uint32_t addr) {
    asm volatile("ldmatrix.sync.aligned.m8n8.x4.shared.b16 {%0,%1,%2,%3}, [%4];"
                 : "=r"(r[0]), "=r"(r[1]), "=r"(r[2]), "=r"(r[3]) : "r"(addr));
}
__device__ __forceinline__ void ldm_x4_t(uint32_t* r, uint32_t addr) {
    asm volatile("ldmatrix.sync.aligned.m8n8.x4.trans.shared.b16 {%0,%1,%2,%3}, [%4];"
                 : "=r"(r[0]), "=r"(r[1]), "=r"(r[2]), "=r"(r[3]) : "r"(addr));
}
__device__ __forceinline__ void mma16816(float* d, const uint32_t* a,
                                         uint32_t b0, uint32_t b1) {
    asm volatile(
        "mma.sync.aligned.m16n8k16.row.col.f32.f16.f16.f32 "
        "{%0,%1,%2,%3}, {%4,%5,%6,%7}, {%8,%9}, {%0,%1,%2,%3};"
        : "+f"(d[0]), "+f"(d[1]), "+f"(d[2]), "+f"(d[3])
        : "r"(a[0]), "r"(a[1]), "r"(a[2]), "r"(a[3]), "r"(b0), "r"(b1));
}
__device__ __forceinline__ uint32_t packh(float lo, float hi) {
    __half2 t = __floats2half2_rn(lo, hi);
    return *(uint32_t*)&t;
}
__device__ __forceinline__ void cp16(uint32_t dst, const void* src) {
    asm volatile("cp.async.cg.shared.global [%0], [%1], 16;"
                 :: "r"(dst), "l"(src));
}
__device__ __forceinline__ float ex2(float x) {
    float y;
    asm("ex2.approx.f32 %0, %1;" : "=f"(y) : "f"(x));
    return y;
}
#define CP_COMMIT() asm volatile("cp.async.commit_group;" ::: "memory")
#define CP_WAIT1()  asm volatile("cp.async.wait_group 1;" ::: "memory")
#define CP_WAIT0()  asm volatile("cp.async.wait_group 0;" ::: "memory")
#define SWZ(b) ((b) ^ (((b) >> 3) & 0x70))
// 16x16 subtile layout for a tile with KCH=64 halves per row
#define SUBT64(r, u) ((((r) >> 4) * 4 + ((u) >> 1)) * 512 + ((r) & 15) * 32 + ((u) & 1) * 16)

// 0.125 * log2(e)
#define SCALE_LOG2E 0.180336880f

// ---------------------------------------------------------------------------
// Split / conversion kernels
// ---------------------------------------------------------------------------
__global__ void split_x_kernel(const float* __restrict__ s) {
    int i = blockIdx.x * 256 + threadIdx.x;
    float a = s[i];
    __half h = __float2half_rn(a);
    g_xh[i] = h;
    g_xl[i] = __float2half_rn(a - __half2float(h));
}
// transpose [K,N] fp32 -> [N,K] fp16 (weights single precision)
template <int W>
__global__ void split_tr_kernel(const float* __restrict__ s, int Kd, int Nd) {
    __shared__ float t[32][33];
    int nb = blockIdx.x * 32, kb = blockIdx.y * 32;
    int tx = threadIdx.x & 31, ty = threadIdx.x >> 5;   // 32 x 8
    for (int r = ty; r < 32; r += 8)
        t[r][tx] = s[(size_t)(kb + r) * Nd + nb + tx];
    __syncthreads();
    __half* hi = W ? g_wph : g_wah;
    for (int r = ty; r < 32; r += 8) {
        size_t o = (size_t)(nb + r) * Kd + kb + tx;
        hi[o] = __float2half_rn(t[tx][r]);
    }
}

#define KCH    64
#define NKCH   (K_ / KCH)          // 12

// ---------------------------------------------------------------------------
// QKV GEMM v8: CTA 128x256, K-chunk 64, 8 warps (2m x 4n, 256 threads),
// warp tile 64x64 (acc=128 regs). 2-stage cp.async + fragment double-buffering.
// A-lo pass only on Q columns (n0 < C_). 1 CTA/SM (128KB smem), grid 9x64.
// Stage: Ah 16K | Al 16K | B 32K.
// ---------------------------------------------------------------------------
#define QSTAGE 65536
#define SMQ    (2 * QSTAGE)        // 131072

__global__ __launch_bounds__(256)
void hgemm_qkv(const float* __restrict__ bias)
{
    extern __shared__ char smem[];
    const uint32_t sb = smem_to_u32(smem);
    const int tid  = threadIdx.x;
    const int lane = tid & 31;
    const int w    = tid >> 5;
    const int mw   = w & 1;        // 2 m-warps (64 rows each)
    const int nw   = w >> 1;       // 4 n-warps (64 cols each)
    const int n0 = blockIdx.x * 256;
    const int m0 = blockIdx.y * 128;

    const bool use_lo = (n0 < C_);   // 256-wide blocks don't straddle 768

    float acc[4][8][4];           // [mt 16-row][j n8][quad] = 128 regs
#pragma unroll
    for (int i = 0; i < 4; i++)
#pragma unroll
        for (int j = 0; j < 8; j++)
#pragma unroll
            for (int q = 0; q < 4; q++) acc[i][j][q] = 0.f;

    auto issue = [&](int stage, int c) {
        const int kk = c * KCH;
        const uint32_t sbase = sb + stage * QSTAGE;
        // A hi (its 0-3) + A lo (its 4-7, if use_lo): 128 rows x 8 u each
#pragma unroll
        for (int it = 0; it < 8; it++) {
            if (it >= 4 && !use_lo) break;
            int idx = it * 256 + tid;
            int hl = idx >> 10, rem = idx & 1023;
            int r = rem >> 3, u = rem & 7;
            const __half* src = hl ? g_xl : g_xh;
            cp16(sbase + hl * 16384 + SUBT64(r, u),
                 src + (size_t)(m0 + r) * K_ + kk + u * 8);
        }
        // B: 256 rows x 8 u = 2048 pieces (8 its)
#pragma unroll
        for (int it = 0; it < 8; it++) {
            int idx = it * 256 + tid;
            int r = idx >> 3, u = idx & 7;
            cp16(sbase + 32768 + SUBT64(r, u),
                 g_wah + (size_t)(n0 + r) * K_ + kk + u * 8);
        }
        CP_COMMIT();
    };

    const uint32_t a_in = (lane & 15) * 32 + (lane >> 4) * 16;
    const uint32_t b_in = ((lane & 7) + (lane >> 4) * 8) * 32 + ((lane >> 3) & 1) * 16;

    issue(0, 0);

    for (int c = 0; c < NKCH; c++) {
        CP_WAIT0();
        __syncthreads();
        if (c + 1 < NKCH) issue((c + 1) & 1, c + 1);

        const uint32_t base = sb + (c & 1) * QSTAGE;

        // fragment double-buffering across kc: B + A-hi; A-lo just-in-time
        uint32_t bf[2][16], ah[2][16], al[16];

        auto load_bah = [&](int kc, int buf) {
#pragma unroll
            for (int nt = 0; nt < 4; nt++)
                ldm_x4(&bf[buf][nt * 4],
                       base + 32768 + ((nw * 4 + nt) * 4 + kc) * 512 + b_in);
#pragma unroll
            for (int mt = 0; mt < 4; mt++)
                ldm_x4(&ah[buf][mt * 4],
                       base + ((mw * 4 + mt) * 4 + kc) * 512 + a_in);
        };

        load_bah(0, 0);
#pragma unroll
        for (int kc = 0; kc < 4; kc++) {
            const int cur = kc & 1;
            if (use_lo) {
#pragma unroll
                for (int mt = 0; mt < 4; mt++)
                    ldm_x4(&al[mt * 4],
                           base + 16384 + ((mw * 4 + mt) * 4 + kc) * 512 + a_in);
            }
            if (kc < 3) load_bah(kc + 1, cur ^ 1);
            // hi pass (32 MMAs, independent accumulators)
#pragma unroll
            for (int mt = 0; mt < 4; mt++)
#pragma unroll
                for (int nt = 0; nt < 4; nt++)
#pragma unroll
                    for (int sub = 0; sub < 2; sub++)
                        mma16816(acc[mt][nt * 2 + sub], &ah[cur][mt * 4],
                                 bf[cur][nt * 4 + sub * 2],
                                 bf[cur][nt * 4 + sub * 2 + 1]);
            // lo pass
            if (use_lo) {
#pragma unroll
                for (int mt = 0; mt < 4; mt++)
#pragma unroll
                    for (int nt = 0; nt < 4; nt++)
#pragma unroll
                        for (int sub = 0; sub < 2; sub++)
                            mma16816(acc[mt][nt * 2 + sub], &al[mt * 4],
                                     bf[cur][nt * 4 + sub * 2],
                                     bf[cur][nt * 4 + sub * 2 + 1]);
            }
        }
    }

    // epilogue: q hi/lo, k/v single fp16 into [B,H,T,hd]
    const int row_in = lane >> 2;
    const int col_in = (lane & 3) * 2;
#pragma unroll
    for (int mt = 0; mt < 4; mt++) {
#pragma unroll
        for (int j = 0; j < 8; j++) {
            const int c = n0 + nw * 64 + j * 8 + col_in;
            const float b0v = bias[c], b1v = bias[c + 1];
#pragma unroll
            for (int hf = 0; hf < 2; hf++) {
                const int m = m0 + mw * 64 + mt * 16 + row_in + hf * 8;
                float v0 = acc[mt][j][hf * 2 + 0] + b0v;
                float v1 = acc[mt][j][hf * 2 + 1] + b1v;
                int which = c / C_;
                int cc = c - which * C_;
                int h = cc >> 6, d = cc & 63;
                int b = m >> 10, tt = m & 1023;
                size_t o = ((size_t)(b * H_ + h) * T_ + tt) * HD_ + d;
                if (which == 0) {
                    float h0 = __half2float(__float2half_rn(v0));
                    float h1 = __half2float(__float2half_rn(v1));
                    *(uint32_t*)&g_qh[o] = packh(v0, v1);
                    *(uint32_t*)&g_ql[o] = packh(v0 - h0, v1 - h1);
                } else if (which == 1) {
                    *(uint32_t*)&g_kh[o] = packh(v0, v1);
                } else {
                    *(uint32_t*)&g_vh[o] = packh(v0, v1);
                }
            }
        }
    }
}

// ---------------------------------------------------------------------------
// Proj GEMM (v7 config, single-pass): CTA 128x128, 4 warps 2m x 2n of 64x64,
// 2-stage cp.async + fragment double-buffering. 2 CTAs/SM.
// Stage: A 16K | B 16K (lo slot unused).
// ---------------------------------------------------------------------------
#define PSTAGE 32768
#define SMP    (2 * PSTAGE)        // 65536

__global__ __launch_bounds__(128)
void hgemm_proj(const float* __restrict__ bias, float* __restrict__ Cout)
{
    extern __shared__ char smem[];
    const uint32_t sb = smem_to_u32(smem);
    const int tid  = threadIdx.x;
    const int lane = tid & 31;
    const int w    = tid >> 5;
    const int mw   = w & 1;
    const int nw   = w >> 1;
    const int n0 = blockIdx.x * 128;
    const int m0 = blockIdx.y * 128;

    float acc[4][8][4];
#pragma unroll
    for (int i = 0; i < 4; i++)
#pragma unroll
        for (int j = 0; j < 8; j++)
#pragma unroll
            for (int q = 0; q < 4; q++) acc[i][j][q] = 0.f;

    auto issue = [&](int stage, int c) {
        const int kk = c * KCH;
        const uint32_t sbase = sb + stage * PSTAGE;
#pragma unroll
        for (int it = 0; it < 8; it++) {
            int idx = it * 128 + tid;
            int r = idx >> 3, u = idx & 7;
            cp16(sbase + SUBT64(r, u),
                 g_yh + (size_t)(m0 + r) * K_ + kk + u * 8);
        }
#pragma unroll
        for (int it = 0; it < 8; it++) {
            int idx = it * 128 + tid;
            int r = idx >> 3, u = idx & 7;
            cp16(sbase + 16384 + SUBT64(r, u),
                 g_wph + (size_t)(n0 + r) * K_ + kk + u * 8);
        }
        CP_COMMIT();
    };

    const uint32_t a_in = (lane & 15) * 32 + (lane >> 4) * 16;
    const uint32_t b_in = ((lane & 7) + (lane >> 4) * 8) * 32 + ((lane >> 3) & 1) * 16;

    issue(0, 0);

    for (int c = 0; c < NKCH; c++) {
        CP_WAIT0();
        __syncthreads();
        if (c + 1 < NKCH) issue((c + 1) & 1, c + 1);

        const uint32_t base = sb + (c & 1) * PSTAGE;
        uint32_t bf[2][16], ah[2][16];

        auto load_bah = [&](int kc, int buf) {
#pragma unroll
            for (int nt = 0; nt < 4; nt++)
                ldm_x4(&bf[buf][nt * 4],
                       base + 16384 + ((nw * 4 + nt) * 4 + kc) * 512 + b_in);
#pragma unroll
            for (int mt = 0; mt < 4; mt++)
                ldm_x4(&ah[buf][mt * 4],
                       base + ((mw * 4 + mt) * 4 + kc) * 512 + a_in);
        };

        load_bah(0, 0);
#pragma unroll
        for (int kc = 0; kc < 4; kc++) {
            const int cur = kc & 1;
            if (kc < 3) load_bah(kc + 1, cur ^ 1);
#pragma unroll
            for (int mt = 0; mt < 4; mt++)
#pragma unroll
                for (int nt = 0; nt < 4; nt++)
#pragma unroll
                    for (int sub = 0; sub < 2; sub++)
                        mma16816(acc[mt][nt * 2 + sub], &ah[cur][mt * 4],
                                 bf[cur][nt * 4 + sub * 2],
                                 bf[cur][nt * 4 + sub * 2 + 1]);
        }
    }

    const int row_in = lane >> 2;
    const int col_in = (lane & 3) * 2;
#pragma unroll
    for (int mt = 0; mt < 4; mt++) {
#pragma unroll
        for (int j = 0; j < 8; j++) {
            const int c = n0 + nw * 64 + j * 8 + col_in;
            const float b0v = bias[c], b1v = bias[c + 1];
#pragma unroll
            for (int hf = 0; hf < 2; hf++) {
                const int m = m0 + mw * 64 + mt * 16 + row_in + hf * 8;
                float v0 = acc[mt][j][hf * 2 + 0] + b0v;
                float v1 = acc[mt][j][hf * 2 + 1] + b1v;
                *(float2*)&Cout[(size_t)m * C_ + c] = make_float2(v0, v1);
            }
        }
    }
}

// ---------------------------------------------------------------------------
// HMMA flash attention, causal. CTA = 128 Q-rows, 8 warps (256 threads).
// Grid (T/128 = 8, 96), qt reversed (heavy first). 3-stage cp.async K/V.
// exp via raw ex2.approx with folded 0.125*log2e scale (saves FMA-pipe work).
// ---------------------------------------------------------------------------
#define ATT_SMEM (3 * 16384 + 2 * 16384)   // 81920

__global__ __launch_bounds__(256, 2)
void attn_mma_kernel()
{
    extern __shared__ char smem[];
    const uint32_t sb = smem_to_u32(smem);
    const int tid = threadIdx.x, lane = tid & 31, w = tid >> 5;
    const int qt = gridDim.x - 1 - blockIdx.x;
    const int bh = blockIdx.y;
    const int q0 = qt * 128;
    const size_t base = (size_t)bh * T_ * HD_;
    const int nkt = 2 * qt + 2;

    auto issue_kv = [&](int stage, int kt) {
        const int k0 = kt * 64;
        const uint32_t sbase = sb + stage * 16384;
#pragma unroll
        for (int it = 0; it < 4; it++) {
            int idx = it * 256 + tid;
            int tile = idx >> 9;
            int rem = idx & 511;
            int r = rem >> 3, u = rem & 7;
            const __half* src = tile ? g_vh : g_kh;
            cp16(sbase + tile * 8192 + SWZ(r * 128 + u * 16),
                 src + base + (size_t)(k0 + r) * HD_ + u * 8);
        }
        CP_COMMIT();
    };

    issue_kv(0, 0);
    issue_kv(1, 1);

#pragma unroll
    for (int half = 0; half < 2; half++) {
        const __half* src = half ? g_ql : g_qh;
        uint32_t dstb = 49152 + half * 16384;
#pragma unroll
        for (int it = 0; it < 4; it++) {
            int idx = it * 256 + tid;
            int r = idx >> 3, u = idx & 7;
            uint4 v = *(const uint4*)(src + base + (size_t)(q0 + r) * HD_ + u * 8);
            *(uint4*)(smem + dstb + SWZ(r * 128 + u * 16)) = v;
        }
    }
    __syncthreads();

    uint32_t qh[4][4], ql[4][4];
    {
        uint32_t rowb = (uint32_t)(16 * w + (lane & 7) + ((lane >> 3) & 1) * 8) * 128;
#pragma unroll
        for (int ks = 0; ks < 4; ks++) {
            uint32_t cb = ks * 32 + (lane >> 4) * 16;
            ldm_x4(qh[ks], sb + 49152 + SWZ(rowb + cb));
            ldm_x4(ql[ks], sb + 65536 + SWZ(rowb + cb));
        }
    }

    float oacc[8][4];
#pragma unroll
    for (int i = 0; i < 8; i++)
#pragma unroll
        for (int j = 0; j < 4; j++) oacc[i][j] = 0.f;
    float m_s[2] = {-1e30f, -1e30f};
    float l_s[2] = {0.f, 0.f};

    const int rlo = q0 + 16 * w + (lane >> 2);
    const int rhi = rlo + 8;

    for (int kt = 0; kt < nkt; kt++) {
        const int k0 = kt * 64;
        if (kt + 1 < nkt) { CP_WAIT1(); } else { CP_WAIT0(); }
        __syncthreads();
        if (kt + 2 < nkt) issue_kv((kt + 2) % 3, kt + 2);
        const uint32_t stg = sb + (kt % 3) * 16384;

        // ---- S = Q K^T (2-MMA hi/lo, split passes) ----
        float sacc[8][4];
#pragma unroll
        for (int i = 0; i < 8; i++)
#pragma unroll
            for (int j = 0; j < 4; j++) sacc[i][j] = 0.f;

#pragma unroll
        for (int kt16 = 0; kt16 < 4; kt16++) {
            uint32_t rowb = (uint32_t)(kt16 * 16 + (lane & 7) + (lane >> 4) * 8) * 128;
            uint32_t kf[4][4];
#pragma unroll
            for (int ks = 0; ks < 4; ks++)
                ldm_x4(kf[ks], stg + SWZ(rowb + ks * 32 + ((lane >> 3) & 1) * 16));
#pragma unroll
            for (int ks = 0; ks < 4; ks++)
#pragma unroll
                for (int sub = 0; sub < 2; sub++)
                    mma16816(sacc[kt16 * 2 + sub], qh[ks],
                             kf[ks][sub * 2], kf[ks][sub * 2 + 1]);
#pragma unroll
            for (int ks = 0; ks < 4; ks++)
#pragma unroll
                for (int sub = 0; sub < 2; sub++)
                    mma16816(sacc[kt16 * 2 + sub], ql[ks],
                             kf[ks][sub * 2], kf[ks][sub * 2 + 1]);
        }

        // ---- scale (base-2 domain) + causal mask ----
        const bool need_mask = (k0 + 63 > rlo);
#pragma unroll
        for (int nt = 0; nt < 8; nt++) {
            int cb0 = k0 + nt * 8 + (lane & 3) * 2;
#pragma unroll
            for (int j = 0; j < 4; j++) sacc[nt][j] *= SCALE_LOG2E;
            if (need_mask) {
                if (cb0 > rlo)     sacc[nt][0] = -1e30f;
                if (cb0 + 1 > rlo) sacc[nt][1] = -1e30f;
                if (cb0 > rhi)     sacc[nt][2] = -1e30f;
                if (cb0 + 1 > rhi) sacc[nt][3] = -1e30f;
            }
        }

        // ---- online softmax (base-2) ----
        float tmax0 = -1e30f, tmax1 = -1e30f;
#pragma unroll
        for (int nt = 0; nt < 8; nt++) {
            tmax0 = fmaxf(tmax0, fmaxf(sacc[nt][0], sacc[nt][1]));
            tmax1 = fmaxf(tmax1, fmaxf(sacc[nt][2], sacc[nt][3]));
        }
        tmax0 = fmaxf(tmax0, __shfl_xor_sync(0xffffffff, tmax0, 1));
        tmax0 = fmaxf(tmax0, __shfl_xor_sync(0xffffffff, tmax0, 2));
        tmax1 = fmaxf(tmax1, __shfl_xor_sync(0xffffffff, tmax1, 1));
        tmax1 = fmaxf(tmax1, __shfl_xor_sync(0xffffffff, tmax1, 2));
        float nm0 = fmaxf(m_s[0], tmax0), nm1 = fmaxf(m_s[1], tmax1);
        float al0 = ex2(m_s[0] - nm0), al1 = ex2(m_s[1] - nm1);
        m_s[0] = nm0; m_s[1] = nm1;

        float rs0 = 0.f, rs1 = 0.f;
#pragma unroll
        for (int nt = 0; nt < 8; nt++) {
            sacc[nt][0] = ex2(sacc[nt][0] - nm0);
            sacc[nt][1] = ex2(sacc[nt][1] - nm0);
            sacc[nt][2] = ex2(sacc[nt][2] - nm1);
            sacc[nt][3] = ex2(sacc[nt][3] - nm1);
            rs0 += sacc[nt][0] + sacc[nt][1];
            rs1 += sacc[nt][2] + sacc[nt][3];
        }
        rs0 += __shfl_xor_sync(0xffffffff, rs0, 1);
        rs0 += __shfl_xor_sync(0xffffffff, rs0, 2);
        rs1 += __shfl_xor_sync(0xffffffff, rs1, 1);
        rs1 += __shfl_xor_sync(0xffffffff, rs1, 2);
        l_s[0] = l_s[0] * al0 + rs0;
        l_s[1] = l_s[1] * al1 + rs1;

#pragma unroll
        for (int nt = 0; nt < 8; nt++) {
            oacc[nt][0] *= al0; oacc[nt][1] *= al0;
            oacc[nt][2] *= al1; oacc[nt][3] *= al1;
        }

        // ---- P fragments (single fp16) ----
        uint32_t ph[4][4];
#pragma unroll
        for (int ks = 0; ks < 4; ks++) {
            const float* t0 = sacc[2 * ks];
            const float* t1 = sacc[2 * ks + 1];
            ph[ks][0] = packh(t0[0], t0[1]);
            ph[ks][1] = packh(t0[2], t0[3]);
            ph[ks][2] = packh(t1[0], t1[1]);
            ph[ks][3] = packh(t1[2], t1[3]);
        }

        // ---- O += P V (single-MMA; V via ldmatrix.trans) ----
#pragma unroll
        for (int ks = 0; ks < 4; ks++) {
            uint32_t rowb = (uint32_t)(ks * 16 + (lane & 7) + ((lane >> 3) & 1) * 8) * 128;
            uint32_t vf[4][4];
#pragma unroll
            for (int np = 0; np < 4; np++)
                ldm_x4_t(vf[np], stg + 8192 + SWZ(rowb + np * 32 + (lane >> 4) * 16));
#pragma unroll
            for (int np = 0; np < 4; np++)
#pragma unroll
                for (int sub = 0; sub < 2; sub++)
                    mma16816(oacc[np * 2 + sub], ph[ks],
                             vf[np][sub * 2], vf[np][sub * 2 + 1]);
        }
    }

    // ---- epilogue: y (single fp16) into [B,T,C], merging heads ----
    float inv0 = 1.f / l_s[0], inv1 = 1.f / l_s[1];
    int b = bh / H_, h = bh - b * H_;
    const int col = h * 64 + (lane & 3) * 2;
#pragma unroll
    for (int nt = 0; nt < 8; nt++) {
        float y0 = oacc[nt][0] * inv0, y1 = oacc[nt][1] * inv0;
        float y2 = oacc[nt][2] * inv1, y3 = oacc[nt][3] * inv1;
        size_t o0 = ((size_t)b * T_ + rlo) * C_ + col + nt * 8;
        size_t o1 = ((size_t)b * T_ + rhi) * C_ + col + nt * 8;
        *(uint32_t*)&g_yh[o0] = packh(y0, y1);
        *(uint32_t*)&g_yh[o1] = packh(y2, y3);
    }
}

// ---------------------------------------------------------------------------
extern "C" void kernel_launch(void* const* d_in, const int* in_sizes, int n_in,
                              void* d_out, int out_size)
{
    (void)in_sizes; (void)n_in; (void)out_size;
    const float* x      = (const float*)d_in[0];
    const float* W_attn = (const float*)d_in[1];
    const float* b_attn = (const float*)d_in[2];
    const float* W_proj = (const float*)d_in[3];
    const float* b_proj = (const float*)d_in[4];
    float* out = (float*)d_out;

    // conversions
    split_x_kernel<<<(M_ROWS * K_) / 256, 256>>>(x);
    split_tr_kernel<0><<<dim3(QKV_N / 32, K_ / 32), 256>>>(W_attn, K_, QKV_N);
    split_tr_kernel<1><<<dim3(C_ / 32, K_ / 32), 256>>>(W_proj, K_, C_);

    // 1) QKV GEMM (v8, 128x256 tiles)
    cudaFuncSetAttribute(hgemm_qkv,
                         cudaFuncAttributeMaxDynamicSharedMemorySize, SMQ);
    hgemm_qkv<<<dim3(QKV_N / 256, M_ROWS / 128), 256, SMQ>>>(b_attn);

    // 2) causal flash attention (128-row Q tiles, heavy-first, ex2)
    cudaFuncSetAttribute(attn_mma_kernel,
                         cudaFuncAttributeMaxDynamicSharedMemorySize, ATT_SMEM);
    attn_mma_kernel<<<dim3(T_ / 128, B_ * H_), 256, ATT_SMEM>>>();

    // 3) output projection (single-pass)
    cudaFuncSetAttribute(hgemm_proj,
                         cudaFuncAttributeMaxDynamicSharedMemorySize, SMP);
    hgemm_proj<<<dim3(C_ / 128, M_ROWS / 128), 128, SMP>>>(b_proj, out);
}

// round 16
// speedup vs baseline: 1.3393x; 1.3393x over previous
#include <cuda_runtime.h>
#include <cuda_fp16.h>
#include <cstdint>
#include <cstddef>

// ---------------------------------------------------------------------------
// MultiHeadAttention: y = proj( causal_attention( x @ W_attn + b_attn ) )
// B=8, T=1024, C=768, H=12, hd=64
// HMMA fp16 throughout, fp32 accumulate. All tensors single fp16
// (measured error ladder puts rel_err ~7e-4 < 1e-3).
// GEMMs: v7 shape (CTA 128x128, 4 warps of 64x64, 2-stage cp.async,
// fragment double-buffering). Attention: 128-row Q tiles, ex2 softmax,
// heavy-first schedule.
// ---------------------------------------------------------------------------

#define B_  8
#define T_  1024
#define C_  768
#define H_  12
#define HD_ 64
#define M_ROWS (B_ * T_)          // 8192
#define QKV_N  (3 * C_)           // 2304
#define K_     C_                 // 768

// ---------------- device scratch (no allocation allowed) -------------------
__device__ __half g_qh[B_ * H_ * T_ * HD_];
__device__ __half g_kh[B_ * H_ * T_ * HD_];
__device__ __half g_vh[B_ * H_ * T_ * HD_];

__device__ __half g_xh[M_ROWS * K_];
__device__ __half g_yh[M_ROWS * K_];                      // attn out
__device__ __half g_wah[QKV_N * K_];                      // W_attn^T [N,K]
__device__ __half g_wph[C_ * K_];                         // W_proj^T [N,K]

// ---------------- small PTX helpers (sm_80-level only) ---------------------
__device__ __forceinline__ uint32_t smem_to_u32(const void* p) {
    uint32_t a;
    asm("{ .reg .u64 t; cvta.to.shared.u64 t, %1; cvt.u32.u64 %0, t; }"
        : "=r"(a) : "l"(p));
    return a;
}
__device__ __forceinline__ void ldm_x4(uint32_t* r, uint32_t addr) {
    asm volatile("ldmatrix.sync.aligned.m8n8.x4.shared.b16 {%0,%1,%2,%3}, [%4];"
                 : "=r"(r[0]), "=r"(r[1]), "=r"(r[2]), "=r"(r[3]) : "r"(addr));
}
__device__ __forceinline__ void ldm_x4_t(uint32_t* r, uint32_t addr) {
    asm volatile("ldmatrix.sync.aligned.m8n8.x4.trans.shared.b16 {%0,%1,%2,%3}, [%4];"
                 : "=r"(r[0]), "=r"(r[1]), "=r"(r[2]), "=r"(r[3]) : "r"(addr));
}
__device__ __forceinline__ void mma16816(float* d, const uint32_t* a,
                                         uint32_t b0, uint32_t b1) {
    asm volatile(
        "mma.sync.aligned.m16n8k16.row.col.f32.f16.f16.f32 "
        "{%0,%1,%2,%3}, {%4,%5,%6,%7}, {%8,%9}, {%0,%1,%2,%3};"
        : "+f"(d[0]), "+f"(d[1]), "+f"(d[2]), "+f"(d[3])
        : "r"(a[0]), "r"(a[1]), "r"(a[2]), "r"(a[3]), "r"(b0), "r"(b1));
}
__device__ __forceinline__ uint32_t packh(float lo, float hi) {
    __half2 t = __floats2half2_rn(lo, hi);
    return *(uint32_t*)&t;
}
__device__ __forceinline__ void cp16(uint32_t dst, const void* src) {
    asm volatile("cp.async.cg.shared.global [%0], [%1], 16;"
                 :: "r"(dst), "l"(src));
}
__device__ __forceinline__ float ex2(float x) {
    float y;
    asm("ex2.approx.f32 %0, %1;" : "=f"(y) : "f"(x));
    return y;
}
#define CP_COMMIT() asm volatile("cp.async.commit_group;" ::: "memory")
#define CP_WAIT1()  asm volatile("cp.async.wait_group 1;" ::: "memory")
#define CP_WAIT0()  asm volatile("cp.async.wait_group 0;" ::: "memory")
#define SWZ(b) ((b) ^ (((b) >> 3) & 0x70))
// 16x16 subtile layout for a tile with KCH=64 halves per row
#define SUBT64(r, u) ((((r) >> 4) * 4 + ((u) >> 1)) * 512 + ((r) & 15) * 32 + ((u) & 1) * 16)

// 0.125 * log2(e)
#define SCALE_LOG2E 0.180336880f

// ---------------------------------------------------------------------------
// Conversion kernels
// ---------------------------------------------------------------------------
__global__ void conv_x_kernel(const float* __restrict__ s) {
    int i = blockIdx.x * 256 + threadIdx.x;
    g_xh[i] = __float2half_rn(s[i]);
}
// transpose [K,N] fp32 -> [N,K] fp16
template <int W>
__global__ void conv_tr_kernel(const float* __restrict__ s, int Kd, int Nd) {
    __shared__ float t[32][33];
    int nb = blockIdx.x * 32, kb = blockIdx.y * 32;
    int tx = threadIdx.x & 31, ty = threadIdx.x >> 5;   // 32 x 8
    for (int r = ty; r < 32; r += 8)
        t[r][tx] = s[(size_t)(kb + r) * Nd + nb + tx];
    __syncthreads();
    __half* hi = W ? g_wph : g_wah;
    for (int r = ty; r < 32; r += 8) {
        size_t o = (size_t)(nb + r) * Kd + kb + tx;
        hi[o] = __float2half_rn(t[tx][r]);
    }
}

#define KCH    64
#define NKCH   (K_ / KCH)          // 12

// ---------------------------------------------------------------------------
// HMMA fp16 GEMM (single-pass): CTA 128x128, K-chunk 64, 4 warps (2m x 2n,
// 128 threads), warp tile 64x64 (acc=128 regs). 2-stage cp.async + fragment
// double-buffering. Stage: A 16K | B 16K; 2 stages = 64KB/CTA -> 2 CTAs/SM.
// EPI==0: q/k/v single fp16 [B,H,T,hd].  EPI==1: fp32 row-major out.
// ---------------------------------------------------------------------------
#define HSTAGE 32768
#define SMH    (2 * HSTAGE)        // 65536

template <int EPI>
__global__ __launch_bounds__(128)
void hgemm(const float* __restrict__ bias, float* __restrict__ Cout, int N)
{
    extern __shared__ char smem[];
    const uint32_t sb = smem_to_u32(smem);
    const int tid  = threadIdx.x;
    const int lane = tid & 31;
    const int w    = tid >> 5;
    const int mw   = w & 1;        // 2 m-warps (64 rows each)
    const int nw   = w >> 1;       // 2 n-warps (64 cols each)
    const int n0 = blockIdx.x * 128;
    const int m0 = blockIdx.y * 128;

    const __half* As = (EPI == 0) ? g_xh : g_yh;
    const __half* Bs = (EPI == 0) ? g_wah : g_wph;

    float acc[4][8][4];           // [mt 16-row][j n8][quad] = 128 regs
#pragma unroll
    for (int i = 0; i < 4; i++)
#pragma unroll
        for (int j = 0; j < 8; j++)
#pragma unroll
            for (int q = 0; q < 4; q++) acc[i][j][q] = 0.f;

    auto issue = [&](int stage, int c) {
        const int kk = c * KCH;
        const uint32_t sbase = sb + stage * HSTAGE;
#pragma unroll
        for (int it = 0; it < 8; it++) {
            int idx = it * 128 + tid;
            int r = idx >> 3, u = idx & 7;
            cp16(sbase + SUBT64(r, u),
                 As + (size_t)(m0 + r) * K_ + kk + u * 8);
        }
#pragma unroll
        for (int it = 0; it < 8; it++) {
            int idx = it * 128 + tid;
            int r = idx >> 3, u = idx & 7;
            cp16(sbase + 16384 + SUBT64(r, u),
                 Bs + (size_t)(n0 + r) * K_ + kk + u * 8);
        }
        CP_COMMIT();
    };

    const uint32_t a_in = (lane & 15) * 32 + (lane >> 4) * 16;
    const uint32_t b_in = ((lane & 7) + (lane >> 4) * 8) * 32 + ((lane >> 3) & 1) * 16;

    issue(0, 0);

    for (int c = 0; c < NKCH; c++) {
        CP_WAIT0();
        __syncthreads();
        if (c + 1 < NKCH) issue((c + 1) & 1, c + 1);

        const uint32_t base = sb + (c & 1) * HSTAGE;
        uint32_t bf[2][16], ah[2][16];

        auto load_bah = [&](int kc, int buf) {
#pragma unroll
            for (int nt = 0; nt < 4; nt++)
                ldm_x4(&bf[buf][nt * 4],
                       base + 16384 + ((nw * 4 + nt) * 4 + kc) * 512 + b_in);
#pragma unroll
            for (int mt = 0; mt < 4; mt++)
                ldm_x4(&ah[buf][mt * 4],
                       base + ((mw * 4 + mt) * 4 + kc) * 512 + a_in);
        };

        load_bah(0, 0);
#pragma unroll
        for (int kc = 0; kc < 4; kc++) {
            const int cur = kc & 1;
            if (kc < 3) load_bah(kc + 1, cur ^ 1);
#pragma unroll
            for (int mt = 0; mt < 4; mt++)
#pragma unroll
                for (int nt = 0; nt < 4; nt++)
#pragma unroll
                    for (int sub = 0; sub < 2; sub++)
                        mma16816(acc[mt][nt * 2 + sub], &ah[cur][mt * 4],
                                 bf[cur][nt * 4 + sub * 2],
                                 bf[cur][nt * 4 + sub * 2 + 1]);
        }
    }

    // epilogue
    const int row_in = lane >> 2;
    const int col_in = (lane & 3) * 2;
#pragma unroll
    for (int mt = 0; mt < 4; mt++) {
#pragma unroll
        for (int j = 0; j < 8; j++) {
            const int c = n0 + nw * 64 + j * 8 + col_in;
            const float b0v = bias[c], b1v = bias[c + 1];
#pragma unroll
            for (int hf = 0; hf < 2; hf++) {
                const int m = m0 + mw * 64 + mt * 16 + row_in + hf * 8;
                float v0 = acc[mt][j][hf * 2 + 0] + b0v;
                float v1 = acc[mt][j][hf * 2 + 1] + b1v;
                if (EPI == 0) {
                    int which = c / C_;
                    int cc = c - which * C_;
                    int h = cc >> 6, d = cc & 63;
                    int b = m >> 10, tt = m & 1023;
                    size_t o = ((size_t)(b * H_ + h) * T_ + tt) * HD_ + d;
                    __half* dst = (which == 0) ? g_qh : (which == 1) ? g_kh : g_vh;
                    *(uint32_t*)&dst[o] = packh(v0, v1);
                } else {
                    *(float2*)&Cout[(size_t)m * N + c] = make_float2(v0, v1);
                }
            }
        }
    }
}

// ---------------------------------------------------------------------------
// HMMA flash attention, causal. CTA = 128 Q-rows, 8 warps (256 threads).
// Grid (T/128 = 8, 96), qt reversed (heavy first). 3-stage cp.async K/V
// (16KB/stage: K 8K | V 8K), ONE barrier per kt (nkt = 2*qt+2).
// Q single fp16 at 48K. S = Q K^T single-MMA; O += P V single-MMA.
// ex2 softmax with folded 0.125*log2e scale. smem 64KB -> 2 CTAs/SM.
// ---------------------------------------------------------------------------
#define ATT_SMEM (3 * 16384 + 16384)   // 65536

__global__ __launch_bounds__(256, 2)
void attn_mma_kernel()
{
    extern __shared__ char smem[];
    const uint32_t sb = smem_to_u32(smem);
    const int tid = threadIdx.x, lane = tid & 31, w = tid >> 5;
    const int qt = gridDim.x - 1 - blockIdx.x;   // heavy tiles first
    const int bh = blockIdx.y;
    const int q0 = qt * 128;
    const size_t base = (size_t)bh * T_ * HD_;
    const int nkt = 2 * qt + 2;

    auto issue_kv = [&](int stage, int kt) {
        const int k0 = kt * 64;
        const uint32_t sbase = sb + stage * 16384;
#pragma unroll
        for (int it = 0; it < 4; it++) {
            int idx = it * 256 + tid;       // 0..1023
            int tile = idx >> 9;            // 0..1
            int rem = idx & 511;
            int r = rem >> 3, u = rem & 7;
            const __half* src = tile ? g_vh : g_kh;
            cp16(sbase + tile * 8192 + SWZ(r * 128 + u * 16),
                 src + base + (size_t)(k0 + r) * HD_ + u * 8);
        }
        CP_COMMIT();
    };

    issue_kv(0, 0);
    issue_kv(1, 1);   // nkt >= 2 always

    // ---- load Q tile (128 rows, single fp16) ----
#pragma unroll
    for (int it = 0; it < 4; it++) {
        int idx = it * 256 + tid;       // 0..1023
        int r = idx >> 3, u = idx & 7;  // r 0..127
        uint4 v = *(const uint4*)(g_qh + base + (size_t)(q0 + r) * HD_ + u * 8);
        *(uint4*)(smem + 49152 + SWZ(r * 128 + u * 16)) = v;
    }
    __syncthreads();

    uint32_t qh[4][4];
    {
        uint32_t rowb = (uint32_t)(16 * w + (lane & 7) + ((lane >> 3) & 1) * 8) * 128;
#pragma unroll
        for (int ks = 0; ks < 4; ks++) {
            uint32_t cb = ks * 32 + (lane >> 4) * 16;
            ldm_x4(qh[ks], sb + 49152 + SWZ(rowb + cb));
        }
    }

    float oacc[8][4];
#pragma unroll
    for (int i = 0; i < 8; i++)
#pragma unroll
        for (int j = 0; j < 4; j++) oacc[i][j] = 0.f;
    float m_s[2] = {-1e30f, -1e30f};
    float l_s[2] = {0.f, 0.f};

    const int rlo = q0 + 16 * w + (lane >> 2);
    const int rhi = rlo + 8;

    for (int kt = 0; kt < nkt; kt++) {
        const int k0 = kt * 64;
        if (kt + 1 < nkt) { CP_WAIT1(); } else { CP_WAIT0(); }
        __syncthreads();
        if (kt + 2 < nkt) issue_kv((kt + 2) % 3, kt + 2);
        const uint32_t stg = sb + (kt % 3) * 16384;

        // ---- S = Q K^T (single-MMA) ----
        float sacc[8][4];
#pragma unroll
        for (int i = 0; i < 8; i++)
#pragma unroll
            for (int j = 0; j < 4; j++) sacc[i][j] = 0.f;

#pragma unroll
        for (int kt16 = 0; kt16 < 4; kt16++) {
            uint32_t rowb = (uint32_t)(kt16 * 16 + (lane & 7) + (lane >> 4) * 8) * 128;
            uint32_t kf[4][4];
#pragma unroll
            for (int ks = 0; ks < 4; ks++)
                ldm_x4(kf[ks], stg + SWZ(rowb + ks * 32 + ((lane >> 3) & 1) * 16));
#pragma unroll
            for (int ks = 0; ks < 4; ks++)
#pragma unroll
                for (int sub = 0; sub < 2; sub++)
                    mma16816(sacc[kt16 * 2 + sub], qh[ks],
                             kf[ks][sub * 2], kf[ks][sub * 2 + 1]);
        }

        // ---- scale (base-2 domain) + causal mask (per-warp guard) ----
        const bool need_mask = (k0 + 63 > rlo);
#pragma unroll
        for (int nt = 0; nt < 8; nt++) {
            int cb0 = k0 + nt * 8 + (lane & 3) * 2;
#pragma unroll
            for (int j = 0; j < 4; j++) sacc[nt][j] *= SCALE_LOG2E;
            if (need_mask) {
                if (cb0 > rlo)     sacc[nt][0] = -1e30f;
                if (cb0 + 1 > rlo) sacc[nt][1] = -1e30f;
                if (cb0 > rhi)     sacc[nt][2] = -1e30f;
                if (cb0 + 1 > rhi) sacc[nt][3] = -1e30f;
            }
        }

        // ---- online softmax (base-2) ----
        float tmax0 = -1e30f, tmax1 = -1e30f;
#pragma unroll
        for (int nt = 0; nt < 8; nt++) {
            tmax0 = fmaxf(tmax0, fmaxf(sacc[nt][0], sacc[nt][1]));
            tmax1 = fmaxf(tmax1, fmaxf(sacc[nt][2], sacc[nt][3]));
        }
        tmax0 = fmaxf(tmax0, __shfl_xor_sync(0xffffffff, tmax0, 1));
        tmax0 = fmaxf(tmax0, __shfl_xor_sync(0xffffffff, tmax0, 2));
        tmax1 = fmaxf(tmax1, __shfl_xor_sync(0xffffffff, tmax1, 1));
        tmax1 = fmaxf(tmax1, __shfl_xor_sync(0xffffffff, tmax1, 2));
        float nm0 = fmaxf(m_s[0], tmax0), nm1 = fmaxf(m_s[1], tmax1);
        float al0 = ex2(m_s[0] - nm0), al1 = ex2(m_s[1] - nm1);
        m_s[0] = nm0; m_s[1] = nm1;

        float rs0 = 0.f, rs1 = 0.f;
#pragma unroll
        for (int nt = 0; nt < 8; nt++) {
            sacc[nt][0] = ex2(sacc[nt][0] - nm0);
            sacc[nt][1] = ex2(sacc[nt][1] - nm0);
            sacc[nt][2] = ex2(sacc[nt][2] - nm1);
            sacc[nt][3] = ex2(sacc[nt][3] - nm1);
            rs0 += sacc[nt][0] + sacc[nt][1];
            rs1 += sacc[nt][2] + sacc[nt][3];
        }
        rs0 += __shfl_xor_sync(0xffffffff, rs0, 1);
        rs0 += __shfl_xor_sync(0xffffffff, rs0, 2);
        rs1 += __shfl_xor_sync(0xffffffff, rs1, 1);
        rs1 += __shfl_xor_sync(0xffffffff, rs1, 2);
        l_s[0] = l_s[0] * al0 + rs0;
        l_s[1] = l_s[1] * al1 + rs1;

#pragma unroll
        for (int nt = 0; nt < 8; nt++) {
            oacc[nt][0] *= al0; oacc[nt][1] *= al0;
            oacc[nt][2] *= al1; oacc[nt][3] *= al1;
        }

        // ---- P fragments (single fp16) ----
        uint32_t ph[4][4];
#pragma unroll
        for (int ks = 0; ks < 4; ks++) {
            const float* t0 = sacc[2 * ks];
            const float* t1 = sacc[2 * ks + 1];
            ph[ks][0] = packh(t0[0], t0[1]);
            ph[ks][1] = packh(t0[2], t0[3]);
            ph[ks][2] = packh(t1[0], t1[1]);
            ph[ks][3] = packh(t1[2], t1[3]);
        }

        // ---- O += P V (single-MMA; V via ldmatrix.trans) ----
#pragma unroll
        for (int ks = 0; ks < 4; ks++) {
            uint32_t rowb = (uint32_t)(ks * 16 + (lane & 7) + ((lane >> 3) & 1) * 8) * 128;
            uint32_t vf[4][4];
#pragma unroll
            for (int np = 0; np < 4; np++)
                ldm_x4_t(vf[np], stg + 8192 + SWZ(rowb + np * 32 + (lane >> 4) * 16));
#pragma unroll
            for (int np = 0; np < 4; np++)
#pragma unroll
                for (int sub = 0; sub < 2; sub++)
                    mma16816(oacc[np * 2 + sub], ph[ks],
                             vf[np][sub * 2], vf[np][sub * 2 + 1]);
        }
    }

    // ---- epilogue: y (single fp16) into [B,T,C], merging heads ----
    float inv0 = 1.f / l_s[0], inv1 = 1.f / l_s[1];
    int b = bh / H_, h = bh - b * H_;
    const int col = h * 64 + (lane & 3) * 2;
#pragma unroll
    for (int nt = 0; nt < 8; nt++) {
        float y0 = oacc[nt][0] * inv0, y1 = oacc[nt][1] * inv0;
        float y2 = oacc[nt][2] * inv1, y3 = oacc[nt][3] * inv1;
        size_t o0 = ((size_t)b * T_ + rlo) * C_ + col + nt * 8;
        size_t o1 = ((size_t)b * T_ + rhi) * C_ + col + nt * 8;
        *(uint32_t*)&g_yh[o0] = packh(y0, y1);
        *(uint32_t*)&g_yh[o1] = packh(y2, y3);
    }
}

// ---------------------------------------------------------------------------
extern "C" void kernel_launch(void* const* d_in, const int* in_sizes, int n_in,
                              void* d_out, int out_size)
{
    (void)in_sizes; (void)n_in; (void)out_size;
    const float* x      = (const float*)d_in[0];
    const float* W_attn = (const float*)d_in[1];
    const float* b_attn = (const float*)d_in[2];
    const float* W_proj = (const float*)d_in[3];
    const float* b_proj = (const float*)d_in[4];
    float* out = (float*)d_out;

    // conversions
    conv_x_kernel<<<(M_ROWS * K_) / 256, 256>>>(x);
    conv_tr_kernel<0><<<dim3(QKV_N / 32, K_ / 32), 256>>>(W_attn, K_, QKV_N);
    conv_tr_kernel<1><<<dim3(C_ / 32, K_ / 32), 256>>>(W_proj, K_, C_);

    // 1) QKV GEMM (single-pass fp16)
    cudaFuncSetAttribute(hgemm<0>,
                         cudaFuncAttributeMaxDynamicSharedMemorySize, SMH);
    hgemm<0><<<dim3(QKV_N / 128, M_ROWS / 128), 128, SMH>>>(b_attn, nullptr, QKV_N);

    // 2) causal flash attention (128-row Q tiles, heavy-first, ex2)
    cudaFuncSetAttribute(attn_mma_kernel,
                         cudaFuncAttributeMaxDynamicSharedMemorySize, ATT_SMEM);
    attn_mma_kernel<<<dim3(T_ / 128, B_ * H_), 256, ATT_SMEM>>>();

    // 3) output projection (single-pass fp16)
    cudaFuncSetAttribute(hgemm<1>,
                         cudaFuncAttributeMaxDynamicSharedMemorySize, SMH);
    hgemm<1><<<dim3(C_ / 128, M_ROWS / 128), 128, SMH>>>(b_proj, out, C_);
}

// round 17
// speedup vs baseline: 1.4331x; 1.0700x over previous
#include <cuda_runtime.h>
#include <cuda_fp16.h>
#include <cstdint>
#include <cstddef>

// ---------------------------------------------------------------------------
// MultiHeadAttention: y = proj( causal_attention( x @ W_attn + b_attn ) )
// B=8, T=1024, C=768, H=12, hd=64
// HMMA fp16 throughout, fp32 accumulate. All tensors single fp16
// (measured rel_err ~6.5e-4 < 1e-3).
// GEMMs: CTA 128x128, 4 warps of 64x64, 2-stage cp.async, frag double-buffer.
// Attention v2: 4 warps x 32 Q-rows (K/V fragments amortized 2x), ex2 softmax,
// heavy-first schedule.
// ---------------------------------------------------------------------------

#define B_  8
#define T_  1024
#define C_  768
#define H_  12
#define HD_ 64
#define M_ROWS (B_ * T_)          // 8192
#define QKV_N  (3 * C_)           // 2304
#define K_     C_                 // 768

// ---------------- device scratch (no allocation allowed) -------------------
__device__ __half g_qh[B_ * H_ * T_ * HD_];
__device__ __half g_kh[B_ * H_ * T_ * HD_];
__device__ __half g_vh[B_ * H_ * T_ * HD_];

__device__ __half g_xh[M_ROWS * K_];
__device__ __half g_yh[M_ROWS * K_];                      // attn out
__device__ __half g_wah[QKV_N * K_];                      // W_attn^T [N,K]
__device__ __half g_wph[C_ * K_];                         // W_proj^T [N,K]

// ---------------- small PTX helpers (sm_80-level only) ---------------------
__device__ __forceinline__ uint32_t smem_to_u32(const void* p) {
    uint32_t a;
    asm("{ .reg .u64 t; cvta.to.shared.u64 t, %1; cvt.u32.u64 %0, t; }"
        : "=r"(a) : "l"(p));
    return a;
}
__device__ __forceinline__ void ldm_x4(uint32_t* r, uint32_t addr) {
    asm volatile("ldmatrix.sync.aligned.m8n8.x4.shared.b16 {%0,%1,%2,%3}, [%4];"
                 : "=r"(r[0]), "=r"(r[1]), "=r"(r[2]), "=r"(r[3]) : "r"(addr));
}
__device__ __forceinline__ void ldm_x4_t(uint32_t* r, uint32_t addr) {
    asm volatile("ldmatrix.sync.aligned.m8n8.x4.trans.shared.b16 {%0,%1,%2,%3}, [%4];"
                 : "=r"(r[0]), "=r"(r[1]), "=r"(r[2]), "=r"(r[3]) : "r"(addr));
}
__device__ __forceinline__ void mma16816(float* d, const uint32_t* a,
                                         uint32_t b0, uint32_t b1) {
    asm volatile(
        "mma.sync.aligned.m16n8k16.row.col.f32.f16.f16.f32 "
        "{%0,%1,%2,%3}, {%4,%5,%6,%7}, {%8,%9}, {%0,%1,%2,%3};"
        : "+f"(d[0]), "+f"(d[1]), "+f"(d[2]), "+f"(d[3])
        : "r"(a[0]), "r"(a[1]), "r"(a[2]), "r"(a[3]), "r"(b0), "r"(b1));
}
__device__ __forceinline__ uint32_t packh(float lo, float hi) {
    __half2 t = __floats2half2_rn(lo, hi);
    return *(uint32_t*)&t;
}
__device__ __forceinline__ void cp16(uint32_t dst, const void* src) {
    asm volatile("cp.async.cg.shared.global [%0], [%1], 16;"
                 :: "r"(dst), "l"(src));
}
__device__ __forceinline__ float ex2(float x) {
    float y;
    asm("ex2.approx.f32 %0, %1;" : "=f"(y) : "f"(x));
    return y;
}
#define CP_COMMIT() asm volatile("cp.async.commit_group;" ::: "memory")
#define CP_WAIT1()  asm volatile("cp.async.wait_group 1;" ::: "memory")
#define CP_WAIT0()  asm volatile("cp.async.wait_group 0;" ::: "memory")
#define SWZ(b) ((b) ^ (((b) >> 3) & 0x70))
// 16x16 subtile layout for a tile with KCH=64 halves per row
#define SUBT64(r, u) ((((r) >> 4) * 4 + ((u) >> 1)) * 512 + ((r) & 15) * 32 + ((u) & 1) * 16)

// 0.125 * log2(e)
#define SCALE_LOG2E 0.180336880f

// ---------------------------------------------------------------------------
// Conversion kernels
// ---------------------------------------------------------------------------
__global__ void conv_x_kernel(const float4* __restrict__ s) {
    int i = blockIdx.x * 256 + threadIdx.x;      // 8 floats per thread
    float4 a = s[2 * i], b = s[2 * i + 1];
    uint4 o;
    o.x = packh(a.x, a.y);
    o.y = packh(a.z, a.w);
    o.z = packh(b.x, b.y);
    o.w = packh(b.z, b.w);
    *(uint4*)&g_xh[(size_t)i * 8] = o;
}
// transpose [K,N] fp32 -> [N,K] fp16
template <int W>
__global__ void conv_tr_kernel(const float* __restrict__ s, int Kd, int Nd) {
    __shared__ float t[32][33];
    int nb = blockIdx.x * 32, kb = blockIdx.y * 32;
    int tx = threadIdx.x & 31, ty = threadIdx.x >> 5;   // 32 x 8
    for (int r = ty; r < 32; r += 8)
        t[r][tx] = s[(size_t)(kb + r) * Nd + nb + tx];
    __syncthreads();
    __half* hi = W ? g_wph : g_wah;
    for (int r = ty; r < 32; r += 8) {
        size_t o = (size_t)(nb + r) * Kd + kb + tx;
        hi[o] = __float2half_rn(t[tx][r]);
    }
}

#define KCH    64
#define NKCH   (K_ / KCH)          // 12

// ---------------------------------------------------------------------------
// HMMA fp16 GEMM (single-pass): CTA 128x128, K-chunk 64, 4 warps (2m x 2n,
// 128 threads), warp tile 64x64 (acc=128 regs). 2-stage cp.async + fragment
// double-buffering. Stage: A 16K | B 16K; 2 stages = 64KB/CTA -> 2 CTAs/SM.
// EPI==0: q/k/v single fp16 [B,H,T,hd].  EPI==1: fp32 row-major out.
// ---------------------------------------------------------------------------
#define HSTAGE 32768
#define SMH    (2 * HSTAGE)        // 65536

template <int EPI>
__global__ __launch_bounds__(128)
void hgemm(const float* __restrict__ bias, float* __restrict__ Cout, int N)
{
    extern __shared__ char smem[];
    const uint32_t sb = smem_to_u32(smem);
    const int tid  = threadIdx.x;
    const int lane = tid & 31;
    const int w    = tid >> 5;
    const int mw   = w & 1;
    const int nw   = w >> 1;
    const int n0 = blockIdx.x * 128;
    const int m0 = blockIdx.y * 128;

    const __half* As = (EPI == 0) ? g_xh : g_yh;
    const __half* Bs = (EPI == 0) ? g_wah : g_wph;

    float acc[4][8][4];
#pragma unroll
    for (int i = 0; i < 4; i++)
#pragma unroll
        for (int j = 0; j < 8; j++)
#pragma unroll
            for (int q = 0; q < 4; q++) acc[i][j][q] = 0.f;

    auto issue = [&](int stage, int c) {
        const int kk = c * KCH;
        const uint32_t sbase = sb + stage * HSTAGE;
#pragma unroll
        for (int it = 0; it < 8; it++) {
            int idx = it * 128 + tid;
            int r = idx >> 3, u = idx & 7;
            cp16(sbase + SUBT64(r, u),
                 As + (size_t)(m0 + r) * K_ + kk + u * 8);
        }
#pragma unroll
        for (int it = 0; it < 8; it++) {
            int idx = it * 128 + tid;
            int r = idx >> 3, u = idx & 7;
            cp16(sbase + 16384 + SUBT64(r, u),
                 Bs + (size_t)(n0 + r) * K_ + kk + u * 8);
        }
        CP_COMMIT();
    };

    const uint32_t a_in = (lane & 15) * 32 + (lane >> 4) * 16;
    const uint32_t b_in = ((lane & 7) + (lane >> 4) * 8) * 32 + ((lane >> 3) & 1) * 16;

    issue(0, 0);

    for (int c = 0; c < NKCH; c++) {
        CP_WAIT0();
        __syncthreads();
        if (c + 1 < NKCH) issue((c + 1) & 1, c + 1);

        const uint32_t base = sb + (c & 1) * HSTAGE;
        uint32_t bf[2][16], ah[2][16];

        auto load_bah = [&](int kc, int buf) {
#pragma unroll
            for (int nt = 0; nt < 4; nt++)
                ldm_x4(&bf[buf][nt * 4],
                       base + 16384 + ((nw * 4 + nt) * 4 + kc) * 512 + b_in);
#pragma unroll
            for (int mt = 0; mt < 4; mt++)
                ldm_x4(&ah[buf][mt * 4],
                       base + ((mw * 4 + mt) * 4 + kc) * 512 + a_in);
        };

        load_bah(0, 0);
#pragma unroll
        for (int kc = 0; kc < 4; kc++) {
            const int cur = kc & 1;
            if (kc < 3) load_bah(kc + 1, cur ^ 1);
#pragma unroll
            for (int mt = 0; mt < 4; mt++)
#pragma unroll
                for (int nt = 0; nt < 4; nt++)
#pragma unroll
                    for (int sub = 0; sub < 2; sub++)
                        mma16816(acc[mt][nt * 2 + sub], &ah[cur][mt * 4],
                                 bf[cur][nt * 4 + sub * 2],
                                 bf[cur][nt * 4 + sub * 2 + 1]);
        }
    }

    // epilogue
    const int row_in = lane >> 2;
    const int col_in = (lane & 3) * 2;
#pragma unroll
    for (int mt = 0; mt < 4; mt++) {
#pragma unroll
        for (int j = 0; j < 8; j++) {
            const int c = n0 + nw * 64 + j * 8 + col_in;
            const float b0v = bias[c], b1v = bias[c + 1];
#pragma unroll
            for (int hf = 0; hf < 2; hf++) {
                const int m = m0 + mw * 64 + mt * 16 + row_in + hf * 8;
                float v0 = acc[mt][j][hf * 2 + 0] + b0v;
                float v1 = acc[mt][j][hf * 2 + 1] + b1v;
                if (EPI == 0) {
                    int which = c / C_;
                    int cc = c - which * C_;
                    int h = cc >> 6, d = cc & 63;
                    int b = m >> 10, tt = m & 1023;
                    size_t o = ((size_t)(b * H_ + h) * T_ + tt) * HD_ + d;
                    __half* dst = (which == 0) ? g_qh : (which == 1) ? g_kh : g_vh;
                    *(uint32_t*)&dst[o] = packh(v0, v1);
                } else {
                    *(float2*)&Cout[(size_t)m * N + c] = make_float2(v0, v1);
                }
            }
        }
    }
}

// ---------------------------------------------------------------------------
// HMMA flash attention v2, causal. CTA = 128 Q-rows, 4 warps (128 threads),
// warp tile 32 rows x 64 keys (K/V fragments amortized over 2 row-groups).
// Grid (T/128 = 8, 96), qt reversed (heavy first). 3-stage cp.async K/V
// (16KB/stage: K 8K | V 8K), ONE barrier per kt (nkt = 2*qt+2).
// Q single fp16 at 48K. ex2 softmax, folded 0.125*log2e scale.
// smem 64KB -> 2 CTAs/SM.
// ---------------------------------------------------------------------------
#define ATT_SMEM (3 * 16384 + 16384)   // 65536

__global__ __launch_bounds__(128, 2)
void attn_mma_kernel()
{
    extern __shared__ char smem[];
    const uint32_t sb = smem_to_u32(smem);
    const int tid = threadIdx.x, lane = tid & 31, w = tid >> 5;
    const int qt = gridDim.x - 1 - blockIdx.x;   // heavy tiles first
    const int bh = blockIdx.y;
    const int q0 = qt * 128;
    const size_t base = (size_t)bh * T_ * HD_;
    const int nkt = 2 * qt + 2;

    // K 512 + V 512 = 1024 x 16B pieces -> 8 its @128 threads
    auto issue_kv = [&](int stage, int kt) {
        const int k0 = kt * 64;
        const uint32_t sbase = sb + stage * 16384;
#pragma unroll
        for (int it = 0; it < 8; it++) {
            int idx = it * 128 + tid;       // 0..1023
            int tile = idx >> 9;            // 0..1
            int rem = idx & 511;
            int r = rem >> 3, u = rem & 7;
            const __half* src = tile ? g_vh : g_kh;
            cp16(sbase + tile * 8192 + SWZ(r * 128 + u * 16),
                 src + base + (size_t)(k0 + r) * HD_ + u * 8);
        }
        CP_COMMIT();
    };

    issue_kv(0, 0);
    issue_kv(1, 1);   // nkt >= 2 always

    // ---- load Q tile (128 rows, single fp16): 1024 pieces, 8 its ----
#pragma unroll
    for (int it = 0; it < 8; it++) {
        int idx = it * 128 + tid;
        int r = idx >> 3, u = idx & 7;
        uint4 v = *(const uint4*)(g_qh + base + (size_t)(q0 + r) * HD_ + u * 8);
        *(uint4*)(smem + 49152 + SWZ(r * 128 + u * 16)) = v;
    }
    __syncthreads();

    // Q fragments: warp rows [32w, 32w+32), 2 m-groups of 16
    uint32_t qh[2][4][4];
    {
#pragma unroll
        for (int mt = 0; mt < 2; mt++) {
            uint32_t rowb = (uint32_t)(32 * w + mt * 16 + (lane & 7) +
                                       ((lane >> 3) & 1) * 8) * 128;
#pragma unroll
            for (int ks = 0; ks < 4; ks++)
                ldm_x4(qh[mt][ks],
                       sb + 49152 + SWZ(rowb + ks * 32 + (lane >> 4) * 16));
        }
    }

    float oacc[2][8][4];
#pragma unroll
    for (int mt = 0; mt < 2; mt++)
#pragma unroll
        for (int i = 0; i < 8; i++)
#pragma unroll
            for (int j = 0; j < 4; j++) oacc[mt][i][j] = 0.f;
    float m_s[2][2] = {{-1e30f, -1e30f}, {-1e30f, -1e30f}};
    float l_s[2][2] = {{0.f, 0.f}, {0.f, 0.f}};

    const int rbase = q0 + 32 * w + (lane >> 2);   // mt adds 16, half adds 8

    for (int kt = 0; kt < nkt; kt++) {
        const int k0 = kt * 64;
        if (kt + 1 < nkt) { CP_WAIT1(); } else { CP_WAIT0(); }
        __syncthreads();
        if (kt + 2 < nkt) issue_kv((kt + 2) % 3, kt + 2);
        const uint32_t stg = sb + (kt % 3) * 16384;

        // ---- S = Q K^T (single-MMA), 2 m-groups share K fragments ----
        float sacc[2][8][4];
#pragma unroll
        for (int mt = 0; mt < 2; mt++)
#pragma unroll
            for (int i = 0; i < 8; i++)
#pragma unroll
                for (int j = 0; j < 4; j++) sacc[mt][i][j] = 0.f;

#pragma unroll
        for (int kt16 = 0; kt16 < 4; kt16++) {
            uint32_t rowb = (uint32_t)(kt16 * 16 + (lane & 7) + (lane >> 4) * 8) * 128;
            uint32_t kf[4][4];
#pragma unroll
            for (int ks = 0; ks < 4; ks++)
                ldm_x4(kf[ks], stg + SWZ(rowb + ks * 32 + ((lane >> 3) & 1) * 16));
#pragma unroll
            for (int mt = 0; mt < 2; mt++)
#pragma unroll
                for (int ks = 0; ks < 4; ks++)
#pragma unroll
                    for (int sub = 0; sub < 2; sub++)
                        mma16816(sacc[mt][kt16 * 2 + sub], qh[mt][ks],
                                 kf[ks][sub * 2], kf[ks][sub * 2 + 1]);
        }

        // ---- scale (base-2) + causal mask + online softmax per m-group ----
        uint32_t ph[2][4][4];
#pragma unroll
        for (int mt = 0; mt < 2; mt++) {
            const int rlo = rbase + mt * 16;
            const int rhi = rlo + 8;
            const bool need_mask = (k0 + 63 > rlo);
#pragma unroll
            for (int nt = 0; nt < 8; nt++) {
                int cb0 = k0 + nt * 8 + (lane & 3) * 2;
#pragma unroll
                for (int j = 0; j < 4; j++) sacc[mt][nt][j] *= SCALE_LOG2E;
                if (need_mask) {
                    if (cb0 > rlo)     sacc[mt][nt][0] = -1e30f;
                    if (cb0 + 1 > rlo) sacc[mt][nt][1] = -1e30f;
                    if (cb0 > rhi)     sacc[mt][nt][2] = -1e30f;
                    if (cb0 + 1 > rhi) sacc[mt][nt][3] = -1e30f;
                }
            }

            float tmax0 = -1e30f, tmax1 = -1e30f;
#pragma unroll
            for (int nt = 0; nt < 8; nt++) {
                tmax0 = fmaxf(tmax0, fmaxf(sacc[mt][nt][0], sacc[mt][nt][1]));
                tmax1 = fmaxf(tmax1, fmaxf(sacc[mt][nt][2], sacc[mt][nt][3]));
            }
            tmax0 = fmaxf(tmax0, __shfl_xor_sync(0xffffffff, tmax0, 1));
            tmax0 = fmaxf(tmax0, __shfl_xor_sync(0xffffffff, tmax0, 2));
            tmax1 = fmaxf(tmax1, __shfl_xor_sync(0xffffffff, tmax1, 1));
            tmax1 = fmaxf(tmax1, __shfl_xor_sync(0xffffffff, tmax1, 2));
            float nm0 = fmaxf(m_s[mt][0], tmax0), nm1 = fmaxf(m_s[mt][1], tmax1);
            float al0 = ex2(m_s[mt][0] - nm0), al1 = ex2(m_s[mt][1] - nm1);
            m_s[mt][0] = nm0; m_s[mt][1] = nm1;

            float rs0 = 0.f, rs1 = 0.f;
#pragma unroll
            for (int nt = 0; nt < 8; nt++) {
                sacc[mt][nt][0] = ex2(sacc[mt][nt][0] - nm0);
                sacc[mt][nt][1] = ex2(sacc[mt][nt][1] - nm0);
                sacc[mt][nt][2] = ex2(sacc[mt][nt][2] - nm1);
                sacc[mt][nt][3] = ex2(sacc[mt][nt][3] - nm1);
                rs0 += sacc[mt][nt][0] + sacc[mt][nt][1];
                rs1 += sacc[mt][nt][2] + sacc[mt][nt][3];
            }
            rs0 += __shfl_xor_sync(0xffffffff, rs0, 1);
            rs0 += __shfl_xor_sync(0xffffffff, rs0, 2);
            rs1 += __shfl_xor_sync(0xffffffff, rs1, 1);
            rs1 += __shfl_xor_sync(0xffffffff, rs1, 2);
            l_s[mt][0] = l_s[mt][0] * al0 + rs0;
            l_s[mt][1] = l_s[mt][1] * al1 + rs1;

#pragma unroll
            for (int nt = 0; nt < 8; nt++) {
                oacc[mt][nt][0] *= al0; oacc[mt][nt][1] *= al0;
                oacc[mt][nt][2] *= al1; oacc[mt][nt][3] *= al1;
            }

            // P fragments (single fp16)
#pragma unroll
            for (int ks = 0; ks < 4; ks++) {
                const float* t0 = sacc[mt][2 * ks];
                const float* t1 = sacc[mt][2 * ks + 1];
                ph[mt][ks][0] = packh(t0[0], t0[1]);
                ph[mt][ks][1] = packh(t0[2], t0[3]);
                ph[mt][ks][2] = packh(t1[0], t1[1]);
                ph[mt][ks][3] = packh(t1[2], t1[3]);
            }
        }

        // ---- O += P V (single-MMA; V shared across m-groups) ----
#pragma unroll
        for (int ks = 0; ks < 4; ks++) {
            uint32_t rowb = (uint32_t)(ks * 16 + (lane & 7) + ((lane >> 3) & 1) * 8) * 128;
            uint32_t vf[4][4];
#pragma unroll
            for (int np = 0; np < 4; np++)
                ldm_x4_t(vf[np], stg + 8192 + SWZ(rowb + np * 32 + (lane >> 4) * 16));
#pragma unroll
            for (int mt = 0; mt < 2; mt++)
#pragma unroll
                for (int np = 0; np < 4; np++)
#pragma unroll
                    for (int sub = 0; sub < 2; sub++)
                        mma16816(oacc[mt][np * 2 + sub], ph[mt][ks],
                                 vf[np][sub * 2], vf[np][sub * 2 + 1]);
        }
    }

    // ---- epilogue: y (single fp16) into [B,T,C], merging heads ----
    int b = bh / H_, h = bh - b * H_;
    const int col = h * 64 + (lane & 3) * 2;
#pragma unroll
    for (int mt = 0; mt < 2; mt++) {
        float inv0 = 1.f / l_s[mt][0], inv1 = 1.f / l_s[mt][1];
        const int rlo = rbase + mt * 16;
        const int rhi = rlo + 8;
#pragma unroll
        for (int nt = 0; nt < 8; nt++) {
            float y0 = oacc[mt][nt][0] * inv0, y1 = oacc[mt][nt][1] * inv0;
            float y2 = oacc[mt][nt][2] * inv1, y3 = oacc[mt][nt][3] * inv1;
            size_t o0 = ((size_t)b * T_ + rlo) * C_ + col + nt * 8;
            size_t o1 = ((size_t)b * T_ + rhi) * C_ + col + nt * 8;
            *(uint32_t*)&g_yh[o0] = packh(y0, y1);
            *(uint32_t*)&g_yh[o1] = packh(y2, y3);
        }
    }
}

// ---------------------------------------------------------------------------
extern "C" void kernel_launch(void* const* d_in, const int* in_sizes, int n_in,
                              void* d_out, int out_size)
{
    (void)in_sizes; (void)n_in; (void)out_size;
    const float* x      = (const float*)d_in[0];
    const float* W_attn = (const float*)d_in[1];
    const float* b_attn = (const float*)d_in[2];
    const float* W_proj = (const float*)d_in[3];
    const float* b_proj = (const float*)d_in[4];
    float* out = (float*)d_out;

    // conversions
    conv_x_kernel<<<(M_ROWS * K_) / 2048, 256>>>((const float4*)x);
    conv_tr_kernel<0><<<dim3(QKV_N / 32, K_ / 32), 256>>>(W_attn, K_, QKV_N);
    conv_tr_kernel<1><<<dim3(C_ / 32, K_ / 32), 256>>>(W_proj, K_, C_);

    // 1) QKV GEMM (single-pass fp16)
    cudaFuncSetAttribute(hgemm<0>,
                         cudaFuncAttributeMaxDynamicSharedMemorySize, SMH);
    hgemm<0><<<dim3(QKV_N / 128, M_ROWS / 128), 128, SMH>>>(b_attn, nullptr, QKV_N);

    // 2) causal flash attention v2 (32-row warps, heavy-first, ex2)
    cudaFuncSetAttribute(attn_mma_kernel,
                         cudaFuncAttributeMaxDynamicSharedMemorySize, ATT_SMEM);
    attn_mma_kernel<<<dim3(T_ / 128, B_ * H_), 128, ATT_SMEM>>>();

    // 3) output projection (single-pass fp16)
    cudaFuncSetAttribute(hgemm<1>,
                         cudaFuncAttributeMaxDynamicSharedMemorySize, SMH);
    hgemm<1><<<dim3(C_ / 128, M_ROWS / 128), 128, SMH>>>(b_proj, out, C_);
}